// round 3
// baseline (speedup 1.0000x reference)
#include <cuda_runtime.h>
#include <math.h>

// Problem constants
#define B_  2
#define T_  2048
#define E_  1024
#define H_  16
#define HD_ 64
#define BT_ (B_ * T_)      // 4096

// ---------------------------------------------------------------------------
// Scratch (static device globals: allocation-free, harness-legal)
// ---------------------------------------------------------------------------
__device__ float g_h  [BT_ * E_];        // layernorm output (reused for ln1, ln2)
__device__ float g_qkv[BT_ * 3 * E_];    // qkv projection
__device__ float g_y  [BT_ * E_];        // attention output (merged heads)
__device__ float g_x1 [BT_ * E_];        // x + attn_proj (residual 1)
__device__ float g_fc [BT_ * 4 * E_];    // gelu(fc) activations

// ---------------------------------------------------------------------------
// LayerNorm: one block per row of E=1024, 256 threads, float4
// ---------------------------------------------------------------------------
__global__ __launch_bounds__(256) void ln_kernel(
    const float* __restrict__ x, const float* __restrict__ g,
    const float* __restrict__ bta, float* __restrict__ out)
{
    const int row = blockIdx.x;
    const int tid = threadIdx.x;
    const float4 v = reinterpret_cast<const float4*>(x + (size_t)row * E_)[tid];

    float s  = v.x + v.y + v.z + v.w;
    float ss = v.x * v.x + v.y * v.y + v.z * v.z + v.w * v.w;

    __shared__ float red[16];
    #pragma unroll
    for (int o = 16; o; o >>= 1) {
        s  += __shfl_xor_sync(0xffffffffu, s,  o);
        ss += __shfl_xor_sync(0xffffffffu, ss, o);
    }
    if ((tid & 31) == 0) { red[tid >> 5] = s; red[8 + (tid >> 5)] = ss; }
    __syncthreads();
    if (tid == 0) {
        float a = 0.f, b2 = 0.f;
        #pragma unroll
        for (int i = 0; i < 8; i++) { a += red[i]; b2 += red[8 + i]; }
        red[0] = a; red[8] = b2;
    }
    __syncthreads();

    const float mean = red[0] * (1.0f / (float)E_);
    const float var  = red[8] * (1.0f / (float)E_) - mean * mean;
    const float inv  = rsqrtf(var + 1e-5f);

    const float4 gg = reinterpret_cast<const float4*>(g)[tid];
    const float4 bb = reinterpret_cast<const float4*>(bta)[tid];
    float4 o;
    o.x = (v.x - mean) * inv * gg.x + bb.x;
    o.y = (v.y - mean) * inv * gg.y + bb.y;
    o.z = (v.z - mean) * inv * gg.z + bb.z;
    o.w = (v.w - mean) * inv * gg.w + bb.w;
    reinterpret_cast<float4*>(out + (size_t)row * E_)[tid] = o;
}

// ---------------------------------------------------------------------------
// GELU (tanh approximation, matches reference new_gelu)
// ---------------------------------------------------------------------------
__device__ __forceinline__ float gelu_f(float x) {
    const float c = 0.7978845608028654f;  // sqrt(2/pi)
    float x3 = x * x * x;
    return 0.5f * x * (1.0f + tanhf(c * (x + 0.044715f * x3)));
}

// ---------------------------------------------------------------------------
// SGEMM: C[M,N] = A[M,K] @ Bm[K,N] + bias[N]  (+gelu)(+Res[M,N])
// 128x128 block tile, BK=8, 256 threads, 8x8 per thread.
// All M,N,K used here are multiples of 128/8: no boundary guards needed.
// ---------------------------------------------------------------------------
template<bool GELU, bool RES>
__global__ __launch_bounds__(256) void sgemm_kernel(
    int M, int N, int K,
    const float* __restrict__ A, const float* __restrict__ Bm,
    const float* __restrict__ bias, const float* __restrict__ Res,
    float* __restrict__ C)
{
    const int BM = 128, BN = 128, BK = 8, TM = 8, TN = 8;
    __shared__ float As[BK][BM];
    __shared__ float Bs[BK][BN];

    const int bx = blockIdx.x;  // N tile
    const int by = blockIdx.y;  // M tile
    const int tid = threadIdx.x;
    const int tc = tid % 16;    // thread col (16 across N)
    const int tr = tid / 16;    // thread row (16 down M)

    const float* Ab = A  + (size_t)by * BM * K;
    const float* Bb = Bm + (size_t)bx * BN;

    float acc[TM][TN];
    #pragma unroll
    for (int i = 0; i < TM; i++)
        #pragma unroll
        for (int j = 0; j < TN; j++) acc[i][j] = 0.f;

    const int aRow = tid >> 1;           // 0..127
    const int aCol = (tid & 1) * 4;      // 0 or 4
    const int bRow = tid >> 5;           // 0..7
    const int bCol = (tid & 31) * 4;     // 0..124

    for (int k0 = 0; k0 < K; k0 += BK) {
        float4 a = *reinterpret_cast<const float4*>(Ab + (size_t)aRow * K + k0 + aCol);
        As[aCol + 0][aRow] = a.x;
        As[aCol + 1][aRow] = a.y;
        As[aCol + 2][aRow] = a.z;
        As[aCol + 3][aRow] = a.w;
        float4 b4 = *reinterpret_cast<const float4*>(Bb + (size_t)(k0 + bRow) * N + bCol);
        *reinterpret_cast<float4*>(&Bs[bRow][bCol]) = b4;
        __syncthreads();

        #pragma unroll
        for (int k = 0; k < BK; k++) {
            float ar[TM], br[TN];
            #pragma unroll
            for (int i = 0; i < TM; i++) ar[i] = As[k][tr * TM + i];
            #pragma unroll
            for (int j = 0; j < TN; j++) br[j] = Bs[k][tc * TN + j];
            #pragma unroll
            for (int i = 0; i < TM; i++)
                #pragma unroll
                for (int j = 0; j < TN; j++) acc[i][j] += ar[i] * br[j];
        }
        __syncthreads();
    }

    // Epilogue
    #pragma unroll
    for (int i = 0; i < TM; i++) {
        const int row = by * BM + tr * TM + i;
        #pragma unroll
        for (int j = 0; j < TN; j += 4) {
            const int col = bx * BN + tc * TN + j;
            const float4 bb = *reinterpret_cast<const float4*>(bias + col);
            float4 r;
            r.x = acc[i][j + 0] + bb.x;
            r.y = acc[i][j + 1] + bb.y;
            r.z = acc[i][j + 2] + bb.z;
            r.w = acc[i][j + 3] + bb.w;
            if (GELU) {
                r.x = gelu_f(r.x); r.y = gelu_f(r.y);
                r.z = gelu_f(r.z); r.w = gelu_f(r.w);
            }
            if (RES) {
                const float4 rr = *reinterpret_cast<const float4*>(Res + (size_t)row * N + col);
                r.x += rr.x; r.y += rr.y; r.z += rr.z; r.w += rr.w;
            }
            *reinterpret_cast<float4*>(C + (size_t)row * N + col) = r;
        }
    }
}

// ---------------------------------------------------------------------------
// Causal flash attention, fp32.
// grid: (T/128, H, B); block: 128 threads; thread i owns query row qt*128+i.
// K/V tiles of 64 keys staged in smem (reads are warp-broadcast).
// q row + 64-wide accumulator live in registers; online softmax in 16-chunks.
// ---------------------------------------------------------------------------
__global__ __launch_bounds__(128) void attn_kernel(
    const float* __restrict__ qkv, float* __restrict__ y)
{
    const int qt  = blockIdx.x;
    const int h   = blockIdx.y;
    const int b   = blockIdx.z;
    const int tid = threadIdx.x;
    const int r   = qt * 128 + tid;     // query row within sequence

    __shared__ float Ks[64][68];        // pad 68 to soften store conflicts
    __shared__ float Vs[64][68];

    const float scale = 0.125f;         // 1/sqrt(64)

    // load q row into registers
    float q[64];
    const float* qp = qkv + ((size_t)(b * T_ + r)) * (3 * E_) + h * HD_;
    #pragma unroll
    for (int d = 0; d < 64; d += 4) {
        float4 t = *reinterpret_cast<const float4*>(qp + d);
        q[d] = t.x; q[d + 1] = t.y; q[d + 2] = t.z; q[d + 3] = t.w;
    }

    float acc[64];
    #pragma unroll
    for (int d = 0; d < 64; d++) acc[d] = 0.f;
    float m = -1e30f, l = 0.f;

    const int nkt = (qt + 1) * 2;       // causal: only key tiles up to diagonal
    for (int kt = 0; kt < nkt; kt++) {
        const int j0 = kt * 64;
        // cooperative K/V tile load: thread t covers row t/8 (+16 per iter),
        // bytes [(t%8)*32, +32): fully coalesced 256B per row.
        {
            const int lr0 = tid >> 3;          // 0..15
            const int lc  = (tid & 7) * 8;     // 0,8,...,56
            #pragma unroll
            for (int it = 0; it < 4; it++) {
                const int lr = lr0 + it * 16;
                const float* kp = qkv + ((size_t)(b * T_ + j0 + lr)) * (3 * E_) + E_ + h * HD_ + lc;
                const float* vp = kp + E_;
                *reinterpret_cast<float4*>(&Ks[lr][lc])     = *reinterpret_cast<const float4*>(kp);
                *reinterpret_cast<float4*>(&Ks[lr][lc + 4]) = *reinterpret_cast<const float4*>(kp + 4);
                *reinterpret_cast<float4*>(&Vs[lr][lc])     = *reinterpret_cast<const float4*>(vp);
                *reinterpret_cast<float4*>(&Vs[lr][lc + 4]) = *reinterpret_cast<const float4*>(vp + 4);
            }
        }
        __syncthreads();

        for (int c = 0; c < 4; c++) {
            float s[16];
            #pragma unroll
            for (int j = 0; j < 16; j++) {
                const int kj = c * 16 + j;
                float dot = 0.f;
                #pragma unroll
                for (int d = 0; d < 64; d += 4) {
                    const float4 kk = *reinterpret_cast<const float4*>(&Ks[kj][d]);
                    dot += q[d] * kk.x + q[d + 1] * kk.y + q[d + 2] * kk.z + q[d + 3] * kk.w;
                }
                s[j] = (j0 + kj <= r) ? dot * scale : -1e30f;
            }
            float mn = m;
            #pragma unroll
            for (int j = 0; j < 16; j++) mn = fmaxf(mn, s[j]);
            const float corr = __expf(m - mn);
            l *= corr;
            #pragma unroll
            for (int d = 0; d < 64; d++) acc[d] *= corr;
            #pragma unroll
            for (int j = 0; j < 16; j++) {
                const float p = __expf(s[j] - mn);
                l += p;
                const int kj = c * 16 + j;
                #pragma unroll
                for (int d = 0; d < 64; d += 4) {
                    const float4 vv = *reinterpret_cast<const float4*>(&Vs[kj][d]);
                    acc[d]     += p * vv.x;
                    acc[d + 1] += p * vv.y;
                    acc[d + 2] += p * vv.z;
                    acc[d + 3] += p * vv.w;
                }
            }
            m = mn;
        }
        __syncthreads();
    }

    const float inv = 1.0f / l;
    float* op = y + ((size_t)(b * T_ + r)) * E_ + h * HD_;
    #pragma unroll
    for (int d = 0; d < 64; d += 4) {
        float4 o;
        o.x = acc[d] * inv; o.y = acc[d + 1] * inv;
        o.z = acc[d + 2] * inv; o.w = acc[d + 3] * inv;
        *reinterpret_cast<float4*>(op + d) = o;
    }
}

// ---------------------------------------------------------------------------
// kernel_launch
// Inputs (metadata order): x, ln1_g, ln1_b, w_attn, b_attn, w_proj, b_proj,
//                          ln2_g, ln2_b, w_fc, b_fc, w_fc2, b_fc2
// ---------------------------------------------------------------------------
extern "C" void kernel_launch(void* const* d_in, const int* in_sizes, int n_in,
                              void* d_out, int out_size)
{
    (void)in_sizes; (void)n_in; (void)out_size;
    const float* x      = (const float*)d_in[0];
    const float* ln1_g  = (const float*)d_in[1];
    const float* ln1_b  = (const float*)d_in[2];
    const float* w_attn = (const float*)d_in[3];
    const float* b_attn = (const float*)d_in[4];
    const float* w_proj = (const float*)d_in[5];
    const float* b_proj = (const float*)d_in[6];
    const float* ln2_g  = (const float*)d_in[7];
    const float* ln2_b  = (const float*)d_in[8];
    const float* w_fc   = (const float*)d_in[9];
    const float* b_fc   = (const float*)d_in[10];
    const float* w_fc2  = (const float*)d_in[11];
    const float* b_fc2  = (const float*)d_in[12];
    float* out = (float*)d_out;

    float *h, *qkv, *y, *x1, *fc;
    cudaGetSymbolAddress((void**)&h,   g_h);
    cudaGetSymbolAddress((void**)&qkv, g_qkv);
    cudaGetSymbolAddress((void**)&y,   g_y);
    cudaGetSymbolAddress((void**)&x1,  g_x1);
    cudaGetSymbolAddress((void**)&fc,  g_fc);

    // 1. ln1
    ln_kernel<<<BT_, 256>>>(x, ln1_g, ln1_b, h);
    // 2. qkv = h @ w_attn + b_attn          [4096,1024]x[1024,3072]
    sgemm_kernel<false, false><<<dim3(3 * E_ / 128, BT_ / 128), 256>>>(
        BT_, 3 * E_, E_, h, w_attn, b_attn, nullptr, qkv);
    // 3. causal MHA
    attn_kernel<<<dim3(T_ / 128, H_, B_), 128>>>(qkv, y);
    // 4. x1 = x + y @ w_proj + b_proj       [4096,1024]x[1024,1024]
    sgemm_kernel<false, true><<<dim3(E_ / 128, BT_ / 128), 256>>>(
        BT_, E_, E_, y, w_proj, b_proj, x, x1);
    // 5. ln2
    ln_kernel<<<BT_, 256>>>(x1, ln2_g, ln2_b, h);
    // 6. fc = gelu(h @ w_fc + b_fc)         [4096,1024]x[1024,4096]
    sgemm_kernel<true, false><<<dim3(4 * E_ / 128, BT_ / 128), 256>>>(
        BT_, 4 * E_, E_, h, w_fc, b_fc, nullptr, fc);
    // 7. out = x1 + fc @ w_fc2 + b_fc2      [4096,4096]x[4096,1024]
    sgemm_kernel<false, true><<<dim3(E_ / 128, BT_ / 128), 256>>>(
        BT_, E_, 4 * E_, fc, w_fc2, b_fc2, x1, out);
}

// round 4
// speedup vs baseline: 1.9454x; 1.9454x over previous
#include <cuda_runtime.h>
#include <math.h>

// Problem constants
#define B_  2
#define T_  2048
#define E_  1024
#define H_  16
#define HD_ 64
#define BT_ (B_ * T_)      // 4096

// ---------------------------------------------------------------------------
// Scratch (static device globals: allocation-free, harness-legal)
// ---------------------------------------------------------------------------
__device__ float g_h  [BT_ * E_];        // layernorm output (tf32-rounded)
__device__ float g_qkv[BT_ * 3 * E_];    // qkv projection
__device__ float g_y  [BT_ * E_];        // attention output (tf32-rounded)
__device__ float g_x1 [BT_ * E_];        // x + attn_proj (residual 1)
__device__ float g_fc [BT_ * 4 * E_];    // gelu(fc) activations (tf32-rounded)
__device__ float g_wr [12 * E_ * E_];    // tf32-rounded weights:
// [0, 3E*E)              w_attn
// [3E*E, 4E*E)           w_proj
// [4E*E, 8E*E)           w_fc
// [8E*E, 12E*E)          w_fc2

// ---------------------------------------------------------------------------
// tf32 round-to-nearest helper
// ---------------------------------------------------------------------------
__device__ __forceinline__ float to_tf32(float x) {
    float r;
    asm("cvt.rna.tf32.f32 %0, %1;" : "=f"(r) : "f"(x));
    return r;
}

// ---------------------------------------------------------------------------
// Weight pre-round: out[i] = tf32(in[i]), float4 vectorized
// ---------------------------------------------------------------------------
__global__ __launch_bounds__(256) void round_kernel(
    const float* __restrict__ in, float* __restrict__ out, int n4)
{
    int i = blockIdx.x * blockDim.x + threadIdx.x;
    if (i >= n4) return;
    float4 v = reinterpret_cast<const float4*>(in)[i];
    v.x = to_tf32(v.x); v.y = to_tf32(v.y);
    v.z = to_tf32(v.z); v.w = to_tf32(v.w);
    reinterpret_cast<float4*>(out)[i] = v;
}

// ---------------------------------------------------------------------------
// LayerNorm: one block per row of E=1024, 256 threads, float4.
// Output rounded to tf32 (it is only ever consumed as a GEMM A operand).
// ---------------------------------------------------------------------------
__global__ __launch_bounds__(256) void ln_kernel(
    const float* __restrict__ x, const float* __restrict__ g,
    const float* __restrict__ bta, float* __restrict__ out)
{
    const int row = blockIdx.x;
    const int tid = threadIdx.x;
    const float4 v = reinterpret_cast<const float4*>(x + (size_t)row * E_)[tid];

    float s  = v.x + v.y + v.z + v.w;
    float ss = v.x * v.x + v.y * v.y + v.z * v.z + v.w * v.w;

    __shared__ float red[16];
    #pragma unroll
    for (int o = 16; o; o >>= 1) {
        s  += __shfl_xor_sync(0xffffffffu, s,  o);
        ss += __shfl_xor_sync(0xffffffffu, ss, o);
    }
    if ((tid & 31) == 0) { red[tid >> 5] = s; red[8 + (tid >> 5)] = ss; }
    __syncthreads();
    if (tid == 0) {
        float a = 0.f, b2 = 0.f;
        #pragma unroll
        for (int i = 0; i < 8; i++) { a += red[i]; b2 += red[8 + i]; }
        red[0] = a; red[8] = b2;
    }
    __syncthreads();

    const float mean = red[0] * (1.0f / (float)E_);
    const float var  = red[8] * (1.0f / (float)E_) - mean * mean;
    const float inv  = rsqrtf(var + 1e-5f);

    const float4 gg = reinterpret_cast<const float4*>(g)[tid];
    const float4 bb = reinterpret_cast<const float4*>(bta)[tid];
    float4 o;
    o.x = to_tf32((v.x - mean) * inv * gg.x + bb.x);
    o.y = to_tf32((v.y - mean) * inv * gg.y + bb.y);
    o.z = to_tf32((v.z - mean) * inv * gg.z + bb.z);
    o.w = to_tf32((v.w - mean) * inv * gg.w + bb.w);
    reinterpret_cast<float4*>(out + (size_t)row * E_)[tid] = o;
}

// ---------------------------------------------------------------------------
// GELU (tanh approximation, matches reference new_gelu)
// ---------------------------------------------------------------------------
__device__ __forceinline__ float gelu_f(float x) {
    const float c = 0.7978845608028654f;  // sqrt(2/pi)
    float x3 = x * x * x;
    return 0.5f * x * (1.0f + tanhf(c * (x + 0.044715f * x3)));
}

// ---------------------------------------------------------------------------
// TF32 tensor-core GEMM: C[M,N] = A[M,K] @ Bm[K,N] + bias[N] (+gelu)(+Res)
// A and Bm MUST be pre-rounded to tf32 (producers handle this).
// 128x128 block tile, BK=16, 256 threads (8 warps, 2Mx4N), warp tile 64x32.
// mma.sync.m16n8k8.tf32, fp32 accumulate. 2-stage cp.async pipeline.
// Smem pads: A stride 20 (conflict-free frag loads), B stride 136.
// ---------------------------------------------------------------------------
#define AS_STRIDE 20
#define BS_STRIDE 136

__device__ __forceinline__ void cp16(void* dst, const void* src) {
    unsigned d = (unsigned)__cvta_generic_to_shared(dst);
    asm volatile("cp.async.cg.shared.global [%0], [%1], 16;\n"
                 :: "r"(d), "l"(src));
}

__device__ __forceinline__ void mma_tf32(
    float* d, const unsigned* a, const unsigned* b)
{
    asm volatile(
        "mma.sync.aligned.m16n8k8.row.col.f32.tf32.tf32.f32 "
        "{%0,%1,%2,%3}, {%4,%5,%6,%7}, {%8,%9}, {%0,%1,%2,%3};\n"
        : "+f"(d[0]), "+f"(d[1]), "+f"(d[2]), "+f"(d[3])
        : "r"(a[0]), "r"(a[1]), "r"(a[2]), "r"(a[3]), "r"(b[0]), "r"(b[1]));
}

template<bool GELU, bool RES, bool ROUND>
__global__ __launch_bounds__(256) void tgemm_kernel(
    int M, int N, int K,
    const float* __restrict__ A, const float* __restrict__ Bm,
    const float* __restrict__ bias, const float* __restrict__ Res,
    float* __restrict__ C)
{
    __shared__ float As[2][128 * AS_STRIDE];   // 2 * 10240 B
    __shared__ float Bs[2][16 * BS_STRIDE];    // 2 *  8704 B

    const int bx  = blockIdx.x;   // N tile
    const int by  = blockIdx.y;   // M tile
    const int tid = threadIdx.x;
    const int lane = tid & 31;
    const int w    = tid >> 5;
    const int wm   = (w >> 2) * 64;    // warp row offset in block tile
    const int wn   = (w & 3) * 32;     // warp col offset
    const int lr   = lane >> 2;        // 0..7
    const int lc   = lane & 3;         // 0..3

    const float* Ab = A  + (size_t)by * 128 * K;
    const float* Bb = Bm + (size_t)bx * 128;

    float acc[4][4][4];
    #pragma unroll
    for (int mi = 0; mi < 4; mi++)
        #pragma unroll
        for (int ni = 0; ni < 4; ni++)
            #pragma unroll
            for (int r = 0; r < 4; r++) acc[mi][ni][r] = 0.f;

    const int nt = K / 16;

    // --- prefetch tile t into stage s ---
    #define PREFETCH(t, s) do {                                              \
        const int k0 = (t) * 16;                                             \
        _Pragma("unroll")                                                    \
        for (int i = 0; i < 2; i++) {                                        \
            int idx = tid + i * 256;                                         \
            int row = idx >> 2, c4 = (idx & 3) * 4;                          \
            cp16(&As[s][row * AS_STRIDE + c4],                               \
                 Ab + (size_t)row * K + k0 + c4);                            \
        }                                                                    \
        _Pragma("unroll")                                                    \
        for (int i = 0; i < 2; i++) {                                        \
            int idx = tid + i * 256;                                         \
            int row = idx >> 5, c4 = (idx & 31) * 4;                         \
            cp16(&Bs[s][row * BS_STRIDE + c4],                               \
                 Bb + (size_t)(k0 + row) * N + c4);                          \
        }                                                                    \
    } while (0)

    PREFETCH(0, 0);
    asm volatile("cp.async.commit_group;\n");

    for (int t = 0; t < nt; t++) {
        if (t + 1 < nt) {
            PREFETCH(t + 1, (t + 1) & 1);
            asm volatile("cp.async.commit_group;\n");
            asm volatile("cp.async.wait_group 1;\n");
        } else {
            asm volatile("cp.async.wait_group 0;\n");
        }
        __syncthreads();

        const float* As_ = As[t & 1];
        const float* Bs_ = Bs[t & 1];
        #pragma unroll
        for (int ks = 0; ks < 2; ks++) {
            const int kk = ks * 8;
            unsigned a[4][4], b[4][2];
            #pragma unroll
            for (int mi = 0; mi < 4; mi++) {
                const float* p = As_ + (wm + mi * 16 + lr) * AS_STRIDE + kk + lc;
                a[mi][0] = __float_as_uint(p[0]);
                a[mi][1] = __float_as_uint(p[8 * AS_STRIDE]);
                a[mi][2] = __float_as_uint(p[4]);
                a[mi][3] = __float_as_uint(p[8 * AS_STRIDE + 4]);
            }
            #pragma unroll
            for (int ni = 0; ni < 4; ni++) {
                const float* p = Bs_ + (kk + lc) * BS_STRIDE + wn + ni * 8 + lr;
                b[ni][0] = __float_as_uint(p[0]);
                b[ni][1] = __float_as_uint(p[4 * BS_STRIDE]);
            }
            #pragma unroll
            for (int mi = 0; mi < 4; mi++)
                #pragma unroll
                for (int ni = 0; ni < 4; ni++)
                    mma_tf32(acc[mi][ni], a[mi], b[ni]);
        }
        __syncthreads();
    }
    #undef PREFETCH

    // --- epilogue ---
    #pragma unroll
    for (int mi = 0; mi < 4; mi++) {
        const int r0 = by * 128 + wm + mi * 16 + lr;
        #pragma unroll
        for (int ni = 0; ni < 4; ni++) {
            const int col = bx * 128 + wn + ni * 8 + lc * 2;
            const float b0 = bias[col], b1 = bias[col + 1];
            float v00 = acc[mi][ni][0] + b0, v01 = acc[mi][ni][1] + b1;
            float v10 = acc[mi][ni][2] + b0, v11 = acc[mi][ni][3] + b1;
            if (GELU) {
                v00 = gelu_f(v00); v01 = gelu_f(v01);
                v10 = gelu_f(v10); v11 = gelu_f(v11);
            }
            if (RES) {
                const float2 ra = *reinterpret_cast<const float2*>(
                    Res + (size_t)r0 * N + col);
                const float2 rb = *reinterpret_cast<const float2*>(
                    Res + (size_t)(r0 + 8) * N + col);
                v00 += ra.x; v01 += ra.y; v10 += rb.x; v11 += rb.y;
            }
            if (ROUND) {
                v00 = to_tf32(v00); v01 = to_tf32(v01);
                v10 = to_tf32(v10); v11 = to_tf32(v11);
            }
            *reinterpret_cast<float2*>(C + (size_t)r0 * N + col)
                = make_float2(v00, v01);
            *reinterpret_cast<float2*>(C + (size_t)(r0 + 8) * N + col)
                = make_float2(v10, v11);
        }
    }
}

// ---------------------------------------------------------------------------
// Causal flash attention, fp32 (unchanged from R2 except tf32-rounded output).
// grid: (T/128, H, B); block: 128 threads; thread i owns one query row.
// ---------------------------------------------------------------------------
__global__ __launch_bounds__(128) void attn_kernel(
    const float* __restrict__ qkv, float* __restrict__ y)
{
    const int qt  = blockIdx.x;
    const int h   = blockIdx.y;
    const int b   = blockIdx.z;
    const int tid = threadIdx.x;
    const int r   = qt * 128 + tid;

    __shared__ float Ks[64][68];
    __shared__ float Vs[64][68];

    const float scale = 0.125f;   // 1/sqrt(64)

    float q[64];
    const float* qp = qkv + ((size_t)(b * T_ + r)) * (3 * E_) + h * HD_;
    #pragma unroll
    for (int d = 0; d < 64; d += 4) {
        float4 t = *reinterpret_cast<const float4*>(qp + d);
        q[d] = t.x; q[d + 1] = t.y; q[d + 2] = t.z; q[d + 3] = t.w;
    }

    float acc[64];
    #pragma unroll
    for (int d = 0; d < 64; d++) acc[d] = 0.f;
    float m = -1e30f, l = 0.f;

    const int nkt = (qt + 1) * 2;
    for (int kt = 0; kt < nkt; kt++) {
        const int j0 = kt * 64;
        {
            const int lr0 = tid >> 3;
            const int lc  = (tid & 7) * 8;
            #pragma unroll
            for (int it = 0; it < 4; it++) {
                const int lr = lr0 + it * 16;
                const float* kp = qkv + ((size_t)(b * T_ + j0 + lr)) * (3 * E_)
                                  + E_ + h * HD_ + lc;
                const float* vp = kp + E_;
                *reinterpret_cast<float4*>(&Ks[lr][lc])     = *reinterpret_cast<const float4*>(kp);
                *reinterpret_cast<float4*>(&Ks[lr][lc + 4]) = *reinterpret_cast<const float4*>(kp + 4);
                *reinterpret_cast<float4*>(&Vs[lr][lc])     = *reinterpret_cast<const float4*>(vp);
                *reinterpret_cast<float4*>(&Vs[lr][lc + 4]) = *reinterpret_cast<const float4*>(vp + 4);
            }
        }
        __syncthreads();

        for (int c = 0; c < 4; c++) {
            float s[16];
            #pragma unroll
            for (int j = 0; j < 16; j++) {
                const int kj = c * 16 + j;
                float dot = 0.f;
                #pragma unroll
                for (int d = 0; d < 64; d += 4) {
                    const float4 kk = *reinterpret_cast<const float4*>(&Ks[kj][d]);
                    dot += q[d] * kk.x + q[d + 1] * kk.y + q[d + 2] * kk.z + q[d + 3] * kk.w;
                }
                s[j] = (j0 + kj <= r) ? dot * scale : -1e30f;
            }
            float mn = m;
            #pragma unroll
            for (int j = 0; j < 16; j++) mn = fmaxf(mn, s[j]);
            const float corr = __expf(m - mn);
            l *= corr;
            #pragma unroll
            for (int d = 0; d < 64; d++) acc[d] *= corr;
            #pragma unroll
            for (int j = 0; j < 16; j++) {
                const float p = __expf(s[j] - mn);
                l += p;
                const int kj = c * 16 + j;
                #pragma unroll
                for (int d = 0; d < 64; d += 4) {
                    const float4 vv = *reinterpret_cast<const float4*>(&Vs[kj][d]);
                    acc[d]     += p * vv.x;
                    acc[d + 1] += p * vv.y;
                    acc[d + 2] += p * vv.z;
                    acc[d + 3] += p * vv.w;
                }
            }
            m = mn;
        }
        __syncthreads();
    }

    const float inv = 1.0f / l;
    float* op = y + ((size_t)(b * T_ + r)) * E_ + h * HD_;
    #pragma unroll
    for (int d = 0; d < 64; d += 4) {
        float4 o;
        o.x = to_tf32(acc[d] * inv);     o.y = to_tf32(acc[d + 1] * inv);
        o.z = to_tf32(acc[d + 2] * inv); o.w = to_tf32(acc[d + 3] * inv);
        *reinterpret_cast<float4*>(op + d) = o;
    }
}

// ---------------------------------------------------------------------------
// kernel_launch
// Inputs (metadata order): x, ln1_g, ln1_b, w_attn, b_attn, w_proj, b_proj,
//                          ln2_g, ln2_b, w_fc, b_fc, w_fc2, b_fc2
// ---------------------------------------------------------------------------
extern "C" void kernel_launch(void* const* d_in, const int* in_sizes, int n_in,
                              void* d_out, int out_size)
{
    (void)in_sizes; (void)n_in; (void)out_size;
    const float* x      = (const float*)d_in[0];
    const float* ln1_g  = (const float*)d_in[1];
    const float* ln1_b  = (const float*)d_in[2];
    const float* w_attn = (const float*)d_in[3];
    const float* b_attn = (const float*)d_in[4];
    const float* w_proj = (const float*)d_in[5];
    const float* b_proj = (const float*)d_in[6];
    const float* ln2_g  = (const float*)d_in[7];
    const float* ln2_b  = (const float*)d_in[8];
    const float* w_fc   = (const float*)d_in[9];
    const float* b_fc   = (const float*)d_in[10];
    const float* w_fc2  = (const float*)d_in[11];
    const float* b_fc2  = (const float*)d_in[12];
    float* out = (float*)d_out;

    float *h, *qkv, *y, *x1, *fc, *wr;
    cudaGetSymbolAddress((void**)&h,   g_h);
    cudaGetSymbolAddress((void**)&qkv, g_qkv);
    cudaGetSymbolAddress((void**)&y,   g_y);
    cudaGetSymbolAddress((void**)&x1,  g_x1);
    cudaGetSymbolAddress((void**)&fc,  g_fc);
    cudaGetSymbolAddress((void**)&wr,  g_wr);

    float* wr_attn = wr;
    float* wr_proj = wr + 3 * E_ * E_;
    float* wr_fc   = wr + 4 * E_ * E_;
    float* wr_fc2  = wr + 8 * E_ * E_;

    // 0. pre-round weights to tf32 (RN) — kills tf32-truncation bias
    round_kernel<<<(3 * E_ * E_ / 4 + 255) / 256, 256>>>(w_attn, wr_attn, 3 * E_ * E_ / 4);
    round_kernel<<<(E_ * E_ / 4 + 255) / 256, 256>>>(w_proj, wr_proj, E_ * E_ / 4);
    round_kernel<<<(4 * E_ * E_ / 4 + 255) / 256, 256>>>(w_fc,  wr_fc,  4 * E_ * E_ / 4);
    round_kernel<<<(4 * E_ * E_ / 4 + 255) / 256, 256>>>(w_fc2, wr_fc2, 4 * E_ * E_ / 4);

    // 1. ln1 (tf32-rounded output)
    ln_kernel<<<BT_, 256>>>(x, ln1_g, ln1_b, h);
    // 2. qkv = h @ w_attn + b_attn          [4096,1024]x[1024,3072]
    tgemm_kernel<false, false, false><<<dim3(3 * E_ / 128, BT_ / 128), 256>>>(
        BT_, 3 * E_, E_, h, wr_attn, b_attn, nullptr, qkv);
    // 3. causal MHA (tf32-rounded y)
    attn_kernel<<<dim3(T_ / 128, H_, B_), 128>>>(qkv, y);
    // 4. x1 = x + y @ w_proj + b_proj       [4096,1024]x[1024,1024]
    tgemm_kernel<false, true, false><<<dim3(E_ / 128, BT_ / 128), 256>>>(
        BT_, E_, E_, y, wr_proj, b_proj, x, x1);
    // 5. ln2 (tf32-rounded output)
    ln_kernel<<<BT_, 256>>>(x1, ln2_g, ln2_b, h);
    // 6. fc = tf32(gelu(h @ w_fc + b_fc))   [4096,1024]x[1024,4096]
    tgemm_kernel<true, false, true><<<dim3(4 * E_ / 128, BT_ / 128), 256>>>(
        BT_, 4 * E_, E_, h, wr_fc, b_fc, nullptr, fc);
    // 7. out = x1 + fc @ w_fc2 + b_fc2      [4096,4096]x[4096,1024]
    tgemm_kernel<false, true, false><<<dim3(E_ / 128, BT_ / 128), 256>>>(
        BT_, E_, 4 * E_, fc, wr_fc2, b_fc2, x1, out);
}

// round 6
// speedup vs baseline: 3.8943x; 2.0018x over previous
#include <cuda_runtime.h>
#include <cuda_fp16.h>
#include <math.h>

// Problem constants
#define B_  2
#define T_  2048
#define E_  1024
#define H_  16
#define HD_ 64
#define BT_ (B_ * T_)      // 4096
#define L2E 1.4426950408889634f

// ---------------------------------------------------------------------------
// Scratch (static device globals: allocation-free, harness-legal)
// ---------------------------------------------------------------------------
__device__ float  g_h   [BT_ * E_];       // layernorm output (tf32-rounded)
__device__ __half g_qkvh[BT_ * 3 * E_];   // qkv projection (fp16, for attention)
__device__ float  g_y   [BT_ * E_];       // attention output (tf32-rounded)
__device__ float  g_x1  [BT_ * E_];       // x + attn_proj (residual 1)
__device__ float  g_fc  [BT_ * 4 * E_];   // gelu(fc) activations (tf32-rounded)
__device__ float  g_wr  [12 * E_ * E_];   // tf32-rounded weights

// ---------------------------------------------------------------------------
// Helpers
// ---------------------------------------------------------------------------
__device__ __forceinline__ float to_tf32(float x) {
    float r;
    asm("cvt.rna.tf32.f32 %0, %1;" : "=f"(r) : "f"(x));
    return r;
}

__device__ __forceinline__ void cp16(void* dst, const void* src) {
    unsigned d = (unsigned)__cvta_generic_to_shared(dst);
    asm volatile("cp.async.cg.shared.global [%0], [%1], 16;\n"
                 :: "r"(d), "l"(src));
}

__device__ __forceinline__ unsigned pack_h2(float a, float b) {
    __half2 h = __floats2half2_rn(a, b);
    return *reinterpret_cast<unsigned*>(&h);
}

__device__ __forceinline__ void ldsm4(
    unsigned& r0, unsigned& r1, unsigned& r2, unsigned& r3, const void* p)
{
    unsigned a = (unsigned)__cvta_generic_to_shared(p);
    asm volatile("ldmatrix.sync.aligned.m8n8.x4.shared.b16 {%0,%1,%2,%3}, [%4];"
                 : "=r"(r0), "=r"(r1), "=r"(r2), "=r"(r3) : "r"(a));
}

__device__ __forceinline__ void ldsm4t(
    unsigned& r0, unsigned& r1, unsigned& r2, unsigned& r3, const void* p)
{
    unsigned a = (unsigned)__cvta_generic_to_shared(p);
    asm volatile("ldmatrix.sync.aligned.m8n8.x4.trans.shared.b16 {%0,%1,%2,%3}, [%4];"
                 : "=r"(r0), "=r"(r1), "=r"(r2), "=r"(r3) : "r"(a));
}

__device__ __forceinline__ void mma_f16(
    float* d, const unsigned* a, const unsigned* b)
{
    asm volatile(
        "mma.sync.aligned.m16n8k16.row.col.f32.f16.f16.f32 "
        "{%0,%1,%2,%3}, {%4,%5,%6,%7}, {%8,%9}, {%0,%1,%2,%3};\n"
        : "+f"(d[0]), "+f"(d[1]), "+f"(d[2]), "+f"(d[3])
        : "r"(a[0]), "r"(a[1]), "r"(a[2]), "r"(a[3]), "r"(b[0]), "r"(b[1]));
}

__device__ __forceinline__ void mma_tf32(
    float* d, const unsigned* a, const unsigned* b)
{
    asm volatile(
        "mma.sync.aligned.m16n8k8.row.col.f32.tf32.tf32.f32 "
        "{%0,%1,%2,%3}, {%4,%5,%6,%7}, {%8,%9}, {%0,%1,%2,%3};\n"
        : "+f"(d[0]), "+f"(d[1]), "+f"(d[2]), "+f"(d[3])
        : "r"(a[0]), "r"(a[1]), "r"(a[2]), "r"(a[3]), "r"(b[0]), "r"(b[1]));
}

// ---------------------------------------------------------------------------
// Weight pre-round to tf32
// ---------------------------------------------------------------------------
__global__ __launch_bounds__(256) void round_kernel(
    const float* __restrict__ in, float* __restrict__ out, int n4)
{
    int i = blockIdx.x * blockDim.x + threadIdx.x;
    if (i >= n4) return;
    float4 v = reinterpret_cast<const float4*>(in)[i];
    v.x = to_tf32(v.x); v.y = to_tf32(v.y);
    v.z = to_tf32(v.z); v.w = to_tf32(v.w);
    reinterpret_cast<float4*>(out)[i] = v;
}

// ---------------------------------------------------------------------------
// LayerNorm (tf32-rounded output: only consumed as GEMM A operand)
// ---------------------------------------------------------------------------
__global__ __launch_bounds__(256) void ln_kernel(
    const float* __restrict__ x, const float* __restrict__ g,
    const float* __restrict__ bta, float* __restrict__ out)
{
    const int row = blockIdx.x;
    const int tid = threadIdx.x;
    const float4 v = reinterpret_cast<const float4*>(x + (size_t)row * E_)[tid];

    float s  = v.x + v.y + v.z + v.w;
    float ss = v.x * v.x + v.y * v.y + v.z * v.z + v.w * v.w;

    __shared__ float red[16];
    #pragma unroll
    for (int o = 16; o; o >>= 1) {
        s  += __shfl_xor_sync(0xffffffffu, s,  o);
        ss += __shfl_xor_sync(0xffffffffu, ss, o);
    }
    if ((tid & 31) == 0) { red[tid >> 5] = s; red[8 + (tid >> 5)] = ss; }
    __syncthreads();
    if (tid == 0) {
        float a = 0.f, b2 = 0.f;
        #pragma unroll
        for (int i = 0; i < 8; i++) { a += red[i]; b2 += red[8 + i]; }
        red[0] = a; red[8] = b2;
    }
    __syncthreads();

    const float mean = red[0] * (1.0f / (float)E_);
    const float var  = red[8] * (1.0f / (float)E_) - mean * mean;
    const float inv  = rsqrtf(var + 1e-5f);

    const float4 gg = reinterpret_cast<const float4*>(g)[tid];
    const float4 bb = reinterpret_cast<const float4*>(bta)[tid];
    float4 o;
    o.x = to_tf32((v.x - mean) * inv * gg.x + bb.x);
    o.y = to_tf32((v.y - mean) * inv * gg.y + bb.y);
    o.z = to_tf32((v.z - mean) * inv * gg.z + bb.z);
    o.w = to_tf32((v.w - mean) * inv * gg.w + bb.w);
    reinterpret_cast<float4*>(out + (size_t)row * E_)[tid] = o;
}

__device__ __forceinline__ float gelu_f(float x) {
    const float c = 0.7978845608028654f;  // sqrt(2/pi)
    float x3 = x * x * x;
    return 0.5f * x * (1.0f + tanhf(c * (x + 0.044715f * x3)));
}

// ---------------------------------------------------------------------------
// TF32 tensor-core GEMM (same as R3) + optional fp16 output (HOUT)
// ---------------------------------------------------------------------------
#define AS_STRIDE 20
#define BS_STRIDE 136

template<bool GELU, bool RES, bool ROUND, bool HOUT>
__global__ __launch_bounds__(256) void tgemm_kernel(
    int M, int N, int K,
    const float* __restrict__ A, const float* __restrict__ Bm,
    const float* __restrict__ bias, const float* __restrict__ Res,
    float* __restrict__ C, __half* __restrict__ Ch)
{
    __shared__ float As[2][128 * AS_STRIDE];
    __shared__ float Bs[2][16 * BS_STRIDE];

    const int bx  = blockIdx.x;
    const int by  = blockIdx.y;
    const int tid = threadIdx.x;
    const int lane = tid & 31;
    const int w    = tid >> 5;
    const int wm   = (w >> 2) * 64;
    const int wn   = (w & 3) * 32;
    const int lr   = lane >> 2;
    const int lc   = lane & 3;

    const float* Ab = A  + (size_t)by * 128 * K;
    const float* Bb = Bm + (size_t)bx * 128;

    float acc[4][4][4];
    #pragma unroll
    for (int mi = 0; mi < 4; mi++)
        #pragma unroll
        for (int ni = 0; ni < 4; ni++)
            #pragma unroll
            for (int r = 0; r < 4; r++) acc[mi][ni][r] = 0.f;

    const int nt = K / 16;

    #define PREFETCH(t, s) do {                                              \
        const int k0 = (t) * 16;                                             \
        _Pragma("unroll")                                                    \
        for (int i = 0; i < 2; i++) {                                        \
            int idx = tid + i * 256;                                         \
            int row = idx >> 2, c4 = (idx & 3) * 4;                          \
            cp16(&As[s][row * AS_STRIDE + c4],                               \
                 Ab + (size_t)row * K + k0 + c4);                            \
        }                                                                    \
        _Pragma("unroll")                                                    \
        for (int i = 0; i < 2; i++) {                                        \
            int idx = tid + i * 256;                                         \
            int row = idx >> 5, c4 = (idx & 31) * 4;                         \
            cp16(&Bs[s][row * BS_STRIDE + c4],                               \
                 Bb + (size_t)(k0 + row) * N + c4);                          \
        }                                                                    \
    } while (0)

    PREFETCH(0, 0);
    asm volatile("cp.async.commit_group;\n");

    for (int t = 0; t < nt; t++) {
        if (t + 1 < nt) {
            PREFETCH(t + 1, (t + 1) & 1);
            asm volatile("cp.async.commit_group;\n");
            asm volatile("cp.async.wait_group 1;\n");
        } else {
            asm volatile("cp.async.wait_group 0;\n");
        }
        __syncthreads();

        const float* As_ = As[t & 1];
        const float* Bs_ = Bs[t & 1];
        #pragma unroll
        for (int ks = 0; ks < 2; ks++) {
            const int kk = ks * 8;
            unsigned a[4][4], b[4][2];
            #pragma unroll
            for (int mi = 0; mi < 4; mi++) {
                const float* p = As_ + (wm + mi * 16 + lr) * AS_STRIDE + kk + lc;
                a[mi][0] = __float_as_uint(p[0]);
                a[mi][1] = __float_as_uint(p[8 * AS_STRIDE]);
                a[mi][2] = __float_as_uint(p[4]);
                a[mi][3] = __float_as_uint(p[8 * AS_STRIDE + 4]);
            }
            #pragma unroll
            for (int ni = 0; ni < 4; ni++) {
                const float* p = Bs_ + (kk + lc) * BS_STRIDE + wn + ni * 8 + lr;
                b[ni][0] = __float_as_uint(p[0]);
                b[ni][1] = __float_as_uint(p[4 * BS_STRIDE]);
            }
            #pragma unroll
            for (int mi = 0; mi < 4; mi++)
                #pragma unroll
                for (int ni = 0; ni < 4; ni++)
                    mma_tf32(acc[mi][ni], a[mi], b[ni]);
        }
        __syncthreads();
    }
    #undef PREFETCH

    // --- epilogue ---
    #pragma unroll
    for (int mi = 0; mi < 4; mi++) {
        const int r0 = by * 128 + wm + mi * 16 + lr;
        #pragma unroll
        for (int ni = 0; ni < 4; ni++) {
            const int col = bx * 128 + wn + ni * 8 + lc * 2;
            const float b0 = bias[col], b1 = bias[col + 1];
            float v00 = acc[mi][ni][0] + b0, v01 = acc[mi][ni][1] + b1;
            float v10 = acc[mi][ni][2] + b0, v11 = acc[mi][ni][3] + b1;
            if (GELU) {
                v00 = gelu_f(v00); v01 = gelu_f(v01);
                v10 = gelu_f(v10); v11 = gelu_f(v11);
            }
            if (RES) {
                const float2 ra = *reinterpret_cast<const float2*>(
                    Res + (size_t)r0 * N + col);
                const float2 rb = *reinterpret_cast<const float2*>(
                    Res + (size_t)(r0 + 8) * N + col);
                v00 += ra.x; v01 += ra.y; v10 += rb.x; v11 += rb.y;
            }
            if (HOUT) {
                *reinterpret_cast<__half2*>(Ch + (size_t)r0 * N + col)
                    = __floats2half2_rn(v00, v01);
                *reinterpret_cast<__half2*>(Ch + (size_t)(r0 + 8) * N + col)
                    = __floats2half2_rn(v10, v11);
            } else {
                if (ROUND) {
                    v00 = to_tf32(v00); v01 = to_tf32(v01);
                    v10 = to_tf32(v10); v11 = to_tf32(v11);
                }
                *reinterpret_cast<float2*>(C + (size_t)r0 * N + col)
                    = make_float2(v00, v01);
                *reinterpret_cast<float2*>(C + (size_t)(r0 + 8) * N + col)
                    = make_float2(v10, v11);
            }
        }
    }
}

// ---------------------------------------------------------------------------
// FlashAttention-2 style causal attention, fp16 tensor cores, fp32 accum.
// grid (T/128 [reversed], H, B); block 256 = 8 warps; warp w owns rows
// [qt*128+16w, +16). Key tiles of 64, double-buffered cp.async staging.
// K via ldmatrix (non-trans), V via ldmatrix.trans. P->A frag is free.
// ---------------------------------------------------------------------------
__global__ __launch_bounds__(256) void attn_kernel(
    const __half* __restrict__ qkvh, float* __restrict__ y)
{
    const int qt   = gridDim.x - 1 - blockIdx.x;   // heavy tiles first
    const int h    = blockIdx.y;
    const int b    = blockIdx.z;
    const int tid  = threadIdx.x;
    const int lane = tid & 31;
    const int w    = tid >> 5;
    const int gid  = lane >> 2;
    const int tig  = lane & 3;
    const int rbase = qt * 128 + w * 16;

    __shared__ __half Ks[2][64][72];   // stride 72 halves = 144B (16B-aligned rows)
    __shared__ __half Vs[2][64][72];

    // Q fragments (one-time, from gmem)
    unsigned qa[4][4];
    const __half* qb = qkvh + ((size_t)(b * T_) + rbase) * (3 * E_) + h * HD_;
    #pragma unroll
    for (int ks = 0; ks < 4; ks++) {
        qa[ks][0] = *reinterpret_cast<const unsigned*>(qb + (size_t)gid       * (3 * E_) + ks * 16 + 2 * tig);
        qa[ks][1] = *reinterpret_cast<const unsigned*>(qb + (size_t)(gid + 8) * (3 * E_) + ks * 16 + 2 * tig);
        qa[ks][2] = *reinterpret_cast<const unsigned*>(qb + (size_t)gid       * (3 * E_) + ks * 16 + 8 + 2 * tig);
        qa[ks][3] = *reinterpret_cast<const unsigned*>(qb + (size_t)(gid + 8) * (3 * E_) + ks * 16 + 8 + 2 * tig);
    }

    float o[8][4];
    #pragma unroll
    for (int nf = 0; nf < 8; nf++)
        #pragma unroll
        for (int e = 0; e < 4; e++) o[nf][e] = 0.f;
    float m0 = -1e30f, m1 = -1e30f, l0 = 0.f, l1 = 0.f;
    const float scale = 0.125f;   // 1/sqrt(64)

    const int nkt = 2 * (qt + 1);
    const __half* kvb = qkvh + ((size_t)(b * T_)) * (3 * E_) + E_ + h * HD_;

    // stage tile kt_ into buffer s_ : 2 K-chunks + 2 V-chunks per thread
    #define APREFETCH(kt_, s_) do {                                          \
        _Pragma("unroll")                                                    \
        for (int i = 0; i < 2; i++) {                                        \
            int ch = tid + i * 256;                                          \
            int row = ch >> 3, c8 = (ch & 7) * 8;                            \
            const __half* src = kvb + (size_t)((kt_) * 64 + row) * (3 * E_) + c8; \
            cp16(&Ks[s_][row][c8], src);                                     \
            cp16(&Vs[s_][row][c8], src + E_);                                \
        }                                                                    \
    } while (0)

    APREFETCH(0, 0);
    asm volatile("cp.async.commit_group;\n");

    for (int kt = 0; kt < nkt; kt++) {
        if (kt + 1 < nkt) {
            APREFETCH(kt + 1, (kt + 1) & 1);
            asm volatile("cp.async.commit_group;\n");
            asm volatile("cp.async.wait_group 1;\n");
        } else {
            asm volatile("cp.async.wait_group 0;\n");
        }
        __syncthreads();

        if (kt * 64 <= rbase + 15) {   // warp has at least one unmasked key
            const int st = kt & 1;
            const int g  = lane >> 3;
            const int r  = lane & 7;

            // --- S = Q K^T ---
            float s[8][4];
            #pragma unroll
            for (int nf = 0; nf < 8; nf++)
                #pragma unroll
                for (int e = 0; e < 4; e++) s[nf][e] = 0.f;

            #pragma unroll
            for (int ks = 0; ks < 4; ks++) {
                unsigned kb[8][2];
                #pragma unroll
                for (int j = 0; j < 4; j++) {
                    const __half* p = &Ks[st][8 * (2 * j + (g >> 1)) + r]
                                         [8 * (2 * ks + (g & 1))];
                    ldsm4(kb[2 * j][0], kb[2 * j][1],
                          kb[2 * j + 1][0], kb[2 * j + 1][1], p);
                }
                #pragma unroll
                for (int nf = 0; nf < 8; nf++) mma_f16(s[nf], qa[ks], kb[nf]);
            }

            // --- scale + causal mask ---
            const bool needm = (kt * 64 + 63 > rbase);
            #pragma unroll
            for (int nf = 0; nf < 8; nf++) {
                #pragma unroll
                for (int e = 0; e < 4; e++) {
                    float v = s[nf][e] * scale;
                    if (needm) {
                        const int col = kt * 64 + nf * 8 + 2 * tig + (e & 1);
                        const int row = rbase + gid + ((e >> 1) << 3);
                        if (col > row) v = -1e30f;
                    }
                    s[nf][e] = v;
                }
            }

            // --- online softmax ---
            float mx0 = -1e30f, mx1 = -1e30f;
            #pragma unroll
            for (int nf = 0; nf < 8; nf++) {
                mx0 = fmaxf(mx0, fmaxf(s[nf][0], s[nf][1]));
                mx1 = fmaxf(mx1, fmaxf(s[nf][2], s[nf][3]));
            }
            mx0 = fmaxf(mx0, __shfl_xor_sync(0xffffffffu, mx0, 1));
            mx0 = fmaxf(mx0, __shfl_xor_sync(0xffffffffu, mx0, 2));
            mx1 = fmaxf(mx1, __shfl_xor_sync(0xffffffffu, mx1, 1));
            mx1 = fmaxf(mx1, __shfl_xor_sync(0xffffffffu, mx1, 2));
            const float mn0 = fmaxf(m0, mx0), mn1 = fmaxf(m1, mx1);
            const float corr0 = exp2f((m0 - mn0) * L2E);
            const float corr1 = exp2f((m1 - mn1) * L2E);
            m0 = mn0; m1 = mn1;

            float sum0 = 0.f, sum1 = 0.f;
            unsigned ph[8][2];
            #pragma unroll
            for (int nf = 0; nf < 8; nf++) {
                const float p0 = exp2f((s[nf][0] - mn0) * L2E);
                const float p1 = exp2f((s[nf][1] - mn0) * L2E);
                const float p2 = exp2f((s[nf][2] - mn1) * L2E);
                const float p3 = exp2f((s[nf][3] - mn1) * L2E);
                sum0 += p0 + p1; sum1 += p2 + p3;
                ph[nf][0] = pack_h2(p0, p1);
                ph[nf][1] = pack_h2(p2, p3);
            }
            sum0 += __shfl_xor_sync(0xffffffffu, sum0, 1);
            sum0 += __shfl_xor_sync(0xffffffffu, sum0, 2);
            sum1 += __shfl_xor_sync(0xffffffffu, sum1, 1);
            sum1 += __shfl_xor_sync(0xffffffffu, sum1, 2);
            l0 = l0 * corr0 + sum0;
            l1 = l1 * corr1 + sum1;

            #pragma unroll
            for (int nf = 0; nf < 8; nf++) {
                o[nf][0] *= corr0; o[nf][1] *= corr0;
                o[nf][2] *= corr1; o[nf][3] *= corr1;
            }

            // --- O += P V ---
            #pragma unroll
            for (int ks = 0; ks < 4; ks++) {
                unsigned vb[8][2];
                #pragma unroll
                for (int j = 0; j < 4; j++) {
                    const __half* p = &Vs[st][8 * (2 * ks + (g & 1)) + r]
                                         [8 * (2 * j + (g >> 1))];
                    ldsm4t(vb[2 * j][0], vb[2 * j][1],
                           vb[2 * j + 1][0], vb[2 * j + 1][1], p);
                }
                unsigned pa[4] = { ph[2 * ks][0], ph[2 * ks][1],
                                   ph[2 * ks + 1][0], ph[2 * ks + 1][1] };
                #pragma unroll
                for (int nf = 0; nf < 8; nf++) mma_f16(o[nf], pa, vb[nf]);
            }
        }
        __syncthreads();
    }
    #undef APREFETCH

    // --- write O / l (tf32-rounded: consumed as proj GEMM A operand) ---
    const float inv0 = 1.0f / l0;
    const float inv1 = 1.0f / l1;
    float* yb = y + ((size_t)(b * T_) + rbase) * E_ + h * HD_;
    #pragma unroll
    for (int nf = 0; nf < 8; nf++) {
        const int d = nf * 8 + 2 * tig;
        *reinterpret_cast<float2*>(yb + (size_t)gid * E_ + d)
            = make_float2(to_tf32(o[nf][0] * inv0), to_tf32(o[nf][1] * inv0));
        *reinterpret_cast<float2*>(yb + (size_t)(gid + 8) * E_ + d)
            = make_float2(to_tf32(o[nf][2] * inv1), to_tf32(o[nf][3] * inv1));
    }
}

// ---------------------------------------------------------------------------
// kernel_launch
// ---------------------------------------------------------------------------
extern "C" void kernel_launch(void* const* d_in, const int* in_sizes, int n_in,
                              void* d_out, int out_size)
{
    (void)in_sizes; (void)n_in; (void)out_size;
    const float* x      = (const float*)d_in[0];
    const float* ln1_g  = (const float*)d_in[1];
    const float* ln1_b  = (const float*)d_in[2];
    const float* w_attn = (const float*)d_in[3];
    const float* b_attn = (const float*)d_in[4];
    const float* w_proj = (const float*)d_in[5];
    const float* b_proj = (const float*)d_in[6];
    const float* ln2_g  = (const float*)d_in[7];
    const float* ln2_b  = (const float*)d_in[8];
    const float* w_fc   = (const float*)d_in[9];
    const float* b_fc   = (const float*)d_in[10];
    const float* w_fc2  = (const float*)d_in[11];
    const float* b_fc2  = (const float*)d_in[12];
    float* out = (float*)d_out;

    float *h, *y, *x1, *fc, *wr;
    __half* qkvh;
    cudaGetSymbolAddress((void**)&h,    g_h);
    cudaGetSymbolAddress((void**)&qkvh, g_qkvh);
    cudaGetSymbolAddress((void**)&y,    g_y);
    cudaGetSymbolAddress((void**)&x1,   g_x1);
    cudaGetSymbolAddress((void**)&fc,   g_fc);
    cudaGetSymbolAddress((void**)&wr,   g_wr);

    float* wr_attn = wr;
    float* wr_proj = wr + 3 * E_ * E_;
    float* wr_fc   = wr + 4 * E_ * E_;
    float* wr_fc2  = wr + 8 * E_ * E_;

    // 0. pre-round weights to tf32 (RN)
    round_kernel<<<(3 * E_ * E_ / 4 + 255) / 256, 256>>>(w_attn, wr_attn, 3 * E_ * E_ / 4);
    round_kernel<<<(E_ * E_ / 4 + 255) / 256, 256>>>(w_proj, wr_proj, E_ * E_ / 4);
    round_kernel<<<(4 * E_ * E_ / 4 + 255) / 256, 256>>>(w_fc,  wr_fc,  4 * E_ * E_ / 4);
    round_kernel<<<(4 * E_ * E_ / 4 + 255) / 256, 256>>>(w_fc2, wr_fc2, 4 * E_ * E_ / 4);

    // 1. ln1
    ln_kernel<<<BT_, 256>>>(x, ln1_g, ln1_b, h);
    // 2. qkv (fp16 out) = h @ w_attn + b_attn
    tgemm_kernel<false, false, false, true><<<dim3(3 * E_ / 128, BT_ / 128), 256>>>(
        BT_, 3 * E_, E_, h, wr_attn, b_attn, nullptr, nullptr, qkvh);
    // 3. causal MHA (fp16 tensor cores)
    attn_kernel<<<dim3(T_ / 128, H_, B_), 256>>>(qkvh, y);
    // 4. x1 = x + y @ w_proj + b_proj
    tgemm_kernel<false, true, false, false><<<dim3(E_ / 128, BT_ / 128), 256>>>(
        BT_, E_, E_, y, wr_proj, b_proj, x, x1, nullptr);
    // 5. ln2
    ln_kernel<<<BT_, 256>>>(x1, ln2_g, ln2_b, h);
    // 6. fc = tf32(gelu(h @ w_fc + b_fc))
    tgemm_kernel<true, false, true, false><<<dim3(4 * E_ / 128, BT_ / 128), 256>>>(
        BT_, 4 * E_, E_, h, wr_fc, b_fc, nullptr, fc, nullptr);
    // 7. out = x1 + fc @ w_fc2 + b_fc2
    tgemm_kernel<false, true, false, false><<<dim3(E_ / 128, BT_ / 128), 256>>>(
        BT_, E_, 4 * E_, fc, wr_fc2, b_fc2, x1, out, nullptr);
}

// round 7
// speedup vs baseline: 6.7601x; 1.7359x over previous
#include <cuda_runtime.h>
#include <cuda_fp16.h>
#include <math.h>

// Problem constants
#define B_  2
#define T_  2048
#define E_  1024
#define H_  16
#define HD_ 64
#define BT_ (B_ * T_)      // 4096
#define L2E 1.4426950408889634f

// ---------------------------------------------------------------------------
// Scratch (static device globals: allocation-free, harness-legal)
// ---------------------------------------------------------------------------
__device__ __half g_h   [BT_ * E_];       // layernorm output (fp16)
__device__ __half g_qkvh[BT_ * 3 * E_];   // qkv projection (fp16)
__device__ __half g_y   [BT_ * E_];       // attention output (fp16)
__device__ float  g_x1  [BT_ * E_];       // x + attn_proj (residual 1, fp32)
__device__ __half g_fc  [BT_ * 4 * E_];   // gelu(fc) activations (fp16)
__device__ __half g_wh  [12 * E_ * E_];   // fp16 weights

// ---------------------------------------------------------------------------
// Helpers
// ---------------------------------------------------------------------------
__device__ __forceinline__ void cp16(void* dst, const void* src) {
    unsigned d = (unsigned)__cvta_generic_to_shared(dst);
    asm volatile("cp.async.cg.shared.global [%0], [%1], 16;\n"
                 :: "r"(d), "l"(src));
}

__device__ __forceinline__ unsigned pack_h2(float a, float b) {
    __half2 h = __floats2half2_rn(a, b);
    return *reinterpret_cast<unsigned*>(&h);
}

__device__ __forceinline__ void ldsm4(
    unsigned& r0, unsigned& r1, unsigned& r2, unsigned& r3, const void* p)
{
    unsigned a = (unsigned)__cvta_generic_to_shared(p);
    asm volatile("ldmatrix.sync.aligned.m8n8.x4.shared.b16 {%0,%1,%2,%3}, [%4];"
                 : "=r"(r0), "=r"(r1), "=r"(r2), "=r"(r3) : "r"(a));
}

__device__ __forceinline__ void ldsm4t(
    unsigned& r0, unsigned& r1, unsigned& r2, unsigned& r3, const void* p)
{
    unsigned a = (unsigned)__cvta_generic_to_shared(p);
    asm volatile("ldmatrix.sync.aligned.m8n8.x4.trans.shared.b16 {%0,%1,%2,%3}, [%4];"
                 : "=r"(r0), "=r"(r1), "=r"(r2), "=r"(r3) : "r"(a));
}

__device__ __forceinline__ void mma_f16(
    float* d, const unsigned* a, const unsigned* b)
{
    asm volatile(
        "mma.sync.aligned.m16n8k16.row.col.f32.f16.f16.f32 "
        "{%0,%1,%2,%3}, {%4,%5,%6,%7}, {%8,%9}, {%0,%1,%2,%3};\n"
        : "+f"(d[0]), "+f"(d[1]), "+f"(d[2]), "+f"(d[3])
        : "r"(a[0]), "r"(a[1]), "r"(a[2]), "r"(a[3]), "r"(b[0]), "r"(b[1]));
}

// ---------------------------------------------------------------------------
// Weight convert: fp32 -> fp16
// ---------------------------------------------------------------------------
__global__ __launch_bounds__(256) void f2h_kernel(
    const float* __restrict__ in, __half* __restrict__ out, int n4)
{
    int i = blockIdx.x * blockDim.x + threadIdx.x;
    if (i >= n4) return;
    float4 v = reinterpret_cast<const float4*>(in)[i];
    __half2* o = reinterpret_cast<__half2*>(out) + 2 * i;
    o[0] = __floats2half2_rn(v.x, v.y);
    o[1] = __floats2half2_rn(v.z, v.w);
}

// ---------------------------------------------------------------------------
// LayerNorm: one block per row of E=1024, 256 threads, fp16 output
// ---------------------------------------------------------------------------
__global__ __launch_bounds__(256) void ln_kernel(
    const float* __restrict__ x, const float* __restrict__ g,
    const float* __restrict__ bta, __half* __restrict__ out)
{
    const int row = blockIdx.x;
    const int tid = threadIdx.x;
    const float4 v = reinterpret_cast<const float4*>(x + (size_t)row * E_)[tid];

    float s  = v.x + v.y + v.z + v.w;
    float ss = v.x * v.x + v.y * v.y + v.z * v.z + v.w * v.w;

    __shared__ float red[16];
    #pragma unroll
    for (int o = 16; o; o >>= 1) {
        s  += __shfl_xor_sync(0xffffffffu, s,  o);
        ss += __shfl_xor_sync(0xffffffffu, ss, o);
    }
    if ((tid & 31) == 0) { red[tid >> 5] = s; red[8 + (tid >> 5)] = ss; }
    __syncthreads();
    if (tid == 0) {
        float a = 0.f, b2 = 0.f;
        #pragma unroll
        for (int i = 0; i < 8; i++) { a += red[i]; b2 += red[8 + i]; }
        red[0] = a; red[8] = b2;
    }
    __syncthreads();

    const float mean = red[0] * (1.0f / (float)E_);
    const float var  = red[8] * (1.0f / (float)E_) - mean * mean;
    const float inv  = rsqrtf(var + 1e-5f);

    const float4 gg = reinterpret_cast<const float4*>(g)[tid];
    const float4 bb = reinterpret_cast<const float4*>(bta)[tid];
    __half2* o = reinterpret_cast<__half2*>(out + (size_t)row * E_) + 2 * tid;
    o[0] = __floats2half2_rn((v.x - mean) * inv * gg.x + bb.x,
                             (v.y - mean) * inv * gg.y + bb.y);
    o[1] = __floats2half2_rn((v.z - mean) * inv * gg.z + bb.z,
                             (v.w - mean) * inv * gg.w + bb.w);
}

__device__ __forceinline__ float gelu_f(float x) {
    const float c = 0.7978845608028654f;  // sqrt(2/pi)
    float x3 = x * x * x;
    return 0.5f * x * (1.0f + tanhf(c * (x + 0.044715f * x3)));
}

// ---------------------------------------------------------------------------
// FP16 tensor-core GEMM: C[M,N] = A[M,K] @ Bm[K,N] + bias[N] (+gelu)(+Res)
// A, Bm fp16; accum fp32. 128x128 tile, BK=32, 256 threads (8 warps 2Mx4N),
// warp tile 64x32, mma.m16n8k16, ldmatrix fragments, 2-stage cp.async.
// A rows padded to 40 halves (80B), B rows to 136 halves (272B):
// ldmatrix phase banks 20i/68i mod 32 -> conflict-free.
// ---------------------------------------------------------------------------
#define AS_ 40
#define BS_ 136

template<bool GELU, bool RES, bool HOUT>
__global__ __launch_bounds__(256) void hgemm_kernel(
    int M, int N, int K,
    const __half* __restrict__ A, const __half* __restrict__ Bm,
    const float* __restrict__ bias, const float* __restrict__ Res,
    float* __restrict__ C, __half* __restrict__ Ch)
{
    __shared__ __half As[2][128 * AS_];   // 2 * 10240 B
    __shared__ __half Bs[2][32 * BS_];    // 2 *  8704 B

    const int bx  = blockIdx.x;
    const int by  = blockIdx.y;
    const int tid = threadIdx.x;
    const int lane = tid & 31;
    const int w    = tid >> 5;
    const int wm   = (w >> 2) * 64;
    const int wn   = (w & 3) * 32;
    const int lr   = lane >> 2;        // 0..7  (accum row in 8-grp)
    const int lc   = lane & 3;         // 0..3  (accum col pair)
    const int g    = lane >> 3;        // ldmatrix group
    const int r    = lane & 7;

    const __half* Ab = A  + (size_t)by * 128 * K;
    const __half* Bb = Bm + (size_t)bx * 128;

    float acc[4][4][4];
    #pragma unroll
    for (int mi = 0; mi < 4; mi++)
        #pragma unroll
        for (int ni = 0; ni < 4; ni++)
            #pragma unroll
            for (int e = 0; e < 4; e++) acc[mi][ni][e] = 0.f;

    const int nt = K / 32;

    #define PREFETCH(t, s) do {                                              \
        const int k0 = (t) * 32;                                             \
        _Pragma("unroll")                                                    \
        for (int i = 0; i < 2; i++) {                                        \
            int idx = tid + i * 256;                                         \
            int row = idx >> 2, c8 = (idx & 3) * 8;                          \
            cp16(&As[s][row * AS_ + c8],                                     \
                 Ab + (size_t)row * K + k0 + c8);                            \
        }                                                                    \
        _Pragma("unroll")                                                    \
        for (int i = 0; i < 2; i++) {                                        \
            int idx = tid + i * 256;                                         \
            int row = idx >> 4, c8 = (idx & 15) * 8;                         \
            cp16(&Bs[s][row * BS_ + c8],                                     \
                 Bb + (size_t)(k0 + row) * N + c8);                          \
        }                                                                    \
    } while (0)

    PREFETCH(0, 0);
    asm volatile("cp.async.commit_group;\n");

    for (int t = 0; t < nt; t++) {
        if (t + 1 < nt) {
            PREFETCH(t + 1, (t + 1) & 1);
            asm volatile("cp.async.commit_group;\n");
            asm volatile("cp.async.wait_group 1;\n");
        } else {
            asm volatile("cp.async.wait_group 0;\n");
        }
        __syncthreads();

        const __half* As_p = As[t & 1];
        const __half* Bs_p = Bs[t & 1];
        #pragma unroll
        for (int ks = 0; ks < 2; ks++) {   // two k16 steps per BK=32 tile
            unsigned a[4][4], b[4][2];
            #pragma unroll
            for (int mi = 0; mi < 4; mi++) {
                const __half* p = As_p
                    + (size_t)(wm + mi * 16 + (lane & 15)) * AS_
                    + 16 * ks + 8 * (lane >> 4);
                ldsm4(a[mi][0], a[mi][1], a[mi][2], a[mi][3], p);
            }
            #pragma unroll
            for (int j = 0; j < 2; j++) {
                const __half* p = Bs_p
                    + (size_t)(8 * (2 * ks + (g & 1)) + r) * BS_
                    + wn + 8 * (2 * j + (g >> 1));
                ldsm4t(b[2 * j][0], b[2 * j][1],
                       b[2 * j + 1][0], b[2 * j + 1][1], p);
            }
            #pragma unroll
            for (int mi = 0; mi < 4; mi++)
                #pragma unroll
                for (int ni = 0; ni < 4; ni++)
                    mma_f16(acc[mi][ni], a[mi], b[ni]);
        }
        __syncthreads();
    }
    #undef PREFETCH

    // --- epilogue ---
    #pragma unroll
    for (int mi = 0; mi < 4; mi++) {
        const int r0 = by * 128 + wm + mi * 16 + lr;
        #pragma unroll
        for (int ni = 0; ni < 4; ni++) {
            const int col = bx * 128 + wn + ni * 8 + lc * 2;
            const float b0 = bias[col], b1 = bias[col + 1];
            float v00 = acc[mi][ni][0] + b0, v01 = acc[mi][ni][1] + b1;
            float v10 = acc[mi][ni][2] + b0, v11 = acc[mi][ni][3] + b1;
            if (GELU) {
                v00 = gelu_f(v00); v01 = gelu_f(v01);
                v10 = gelu_f(v10); v11 = gelu_f(v11);
            }
            if (RES) {
                const float2 ra = *reinterpret_cast<const float2*>(
                    Res + (size_t)r0 * N + col);
                const float2 rb = *reinterpret_cast<const float2*>(
                    Res + (size_t)(r0 + 8) * N + col);
                v00 += ra.x; v01 += ra.y; v10 += rb.x; v11 += rb.y;
            }
            if (HOUT) {
                *reinterpret_cast<__half2*>(Ch + (size_t)r0 * N + col)
                    = __floats2half2_rn(v00, v01);
                *reinterpret_cast<__half2*>(Ch + (size_t)(r0 + 8) * N + col)
                    = __floats2half2_rn(v10, v11);
            } else {
                *reinterpret_cast<float2*>(C + (size_t)r0 * N + col)
                    = make_float2(v00, v01);
                *reinterpret_cast<float2*>(C + (size_t)(r0 + 8) * N + col)
                    = make_float2(v10, v11);
            }
        }
    }
}

// ---------------------------------------------------------------------------
// FlashAttention-2 style causal attention, fp16 tensor cores, fp32 accum.
// (unchanged from R5 except fp16 output)
// ---------------------------------------------------------------------------
__global__ __launch_bounds__(256) void attn_kernel(
    const __half* __restrict__ qkvh, __half* __restrict__ y)
{
    const int qt   = gridDim.x - 1 - blockIdx.x;   // heavy tiles first
    const int h    = blockIdx.y;
    const int b    = blockIdx.z;
    const int tid  = threadIdx.x;
    const int lane = tid & 31;
    const int w    = tid >> 5;
    const int gid  = lane >> 2;
    const int tig  = lane & 3;
    const int rbase = qt * 128 + w * 16;

    __shared__ __half Ks[2][64][72];
    __shared__ __half Vs[2][64][72];

    unsigned qa[4][4];
    const __half* qb = qkvh + ((size_t)(b * T_) + rbase) * (3 * E_) + h * HD_;
    #pragma unroll
    for (int ks = 0; ks < 4; ks++) {
        qa[ks][0] = *reinterpret_cast<const unsigned*>(qb + (size_t)gid       * (3 * E_) + ks * 16 + 2 * tig);
        qa[ks][1] = *reinterpret_cast<const unsigned*>(qb + (size_t)(gid + 8) * (3 * E_) + ks * 16 + 2 * tig);
        qa[ks][2] = *reinterpret_cast<const unsigned*>(qb + (size_t)gid       * (3 * E_) + ks * 16 + 8 + 2 * tig);
        qa[ks][3] = *reinterpret_cast<const unsigned*>(qb + (size_t)(gid + 8) * (3 * E_) + ks * 16 + 8 + 2 * tig);
    }

    float o[8][4];
    #pragma unroll
    for (int nf = 0; nf < 8; nf++)
        #pragma unroll
        for (int e = 0; e < 4; e++) o[nf][e] = 0.f;
    float m0 = -1e30f, m1 = -1e30f, l0 = 0.f, l1 = 0.f;
    const float scale = 0.125f;

    const int nkt = 2 * (qt + 1);
    const __half* kvb = qkvh + ((size_t)(b * T_)) * (3 * E_) + E_ + h * HD_;

    #define APREFETCH(kt_, s_) do {                                          \
        _Pragma("unroll")                                                    \
        for (int i = 0; i < 2; i++) {                                        \
            int ch = tid + i * 256;                                          \
            int row = ch >> 3, c8 = (ch & 7) * 8;                            \
            const __half* src = kvb + (size_t)((kt_) * 64 + row) * (3 * E_) + c8; \
            cp16(&Ks[s_][row][c8], src);                                     \
            cp16(&Vs[s_][row][c8], src + E_);                                \
        }                                                                    \
    } while (0)

    APREFETCH(0, 0);
    asm volatile("cp.async.commit_group;\n");

    for (int kt = 0; kt < nkt; kt++) {
        if (kt + 1 < nkt) {
            APREFETCH(kt + 1, (kt + 1) & 1);
            asm volatile("cp.async.commit_group;\n");
            asm volatile("cp.async.wait_group 1;\n");
        } else {
            asm volatile("cp.async.wait_group 0;\n");
        }
        __syncthreads();

        if (kt * 64 <= rbase + 15) {
            const int st = kt & 1;
            const int g  = lane >> 3;
            const int r  = lane & 7;

            float s[8][4];
            #pragma unroll
            for (int nf = 0; nf < 8; nf++)
                #pragma unroll
                for (int e = 0; e < 4; e++) s[nf][e] = 0.f;

            #pragma unroll
            for (int ks = 0; ks < 4; ks++) {
                unsigned kb[8][2];
                #pragma unroll
                for (int j = 0; j < 4; j++) {
                    const __half* p = &Ks[st][8 * (2 * j + (g >> 1)) + r]
                                         [8 * (2 * ks + (g & 1))];
                    ldsm4(kb[2 * j][0], kb[2 * j][1],
                          kb[2 * j + 1][0], kb[2 * j + 1][1], p);
                }
                #pragma unroll
                for (int nf = 0; nf < 8; nf++) mma_f16(s[nf], qa[ks], kb[nf]);
            }

            const bool needm = (kt * 64 + 63 > rbase);
            #pragma unroll
            for (int nf = 0; nf < 8; nf++) {
                #pragma unroll
                for (int e = 0; e < 4; e++) {
                    float v = s[nf][e] * scale;
                    if (needm) {
                        const int col = kt * 64 + nf * 8 + 2 * tig + (e & 1);
                        const int row = rbase + gid + ((e >> 1) << 3);
                        if (col > row) v = -1e30f;
                    }
                    s[nf][e] = v;
                }
            }

            float mx0 = -1e30f, mx1 = -1e30f;
            #pragma unroll
            for (int nf = 0; nf < 8; nf++) {
                mx0 = fmaxf(mx0, fmaxf(s[nf][0], s[nf][1]));
                mx1 = fmaxf(mx1, fmaxf(s[nf][2], s[nf][3]));
            }
            mx0 = fmaxf(mx0, __shfl_xor_sync(0xffffffffu, mx0, 1));
            mx0 = fmaxf(mx0, __shfl_xor_sync(0xffffffffu, mx0, 2));
            mx1 = fmaxf(mx1, __shfl_xor_sync(0xffffffffu, mx1, 1));
            mx1 = fmaxf(mx1, __shfl_xor_sync(0xffffffffu, mx1, 2));
            const float mn0 = fmaxf(m0, mx0), mn1 = fmaxf(m1, mx1);
            const float corr0 = exp2f((m0 - mn0) * L2E);
            const float corr1 = exp2f((m1 - mn1) * L2E);
            m0 = mn0; m1 = mn1;

            float sum0 = 0.f, sum1 = 0.f;
            unsigned ph[8][2];
            #pragma unroll
            for (int nf = 0; nf < 8; nf++) {
                const float p0 = exp2f((s[nf][0] - mn0) * L2E);
                const float p1 = exp2f((s[nf][1] - mn0) * L2E);
                const float p2 = exp2f((s[nf][2] - mn1) * L2E);
                const float p3 = exp2f((s[nf][3] - mn1) * L2E);
                sum0 += p0 + p1; sum1 += p2 + p3;
                ph[nf][0] = pack_h2(p0, p1);
                ph[nf][1] = pack_h2(p2, p3);
            }
            sum0 += __shfl_xor_sync(0xffffffffu, sum0, 1);
            sum0 += __shfl_xor_sync(0xffffffffu, sum0, 2);
            sum1 += __shfl_xor_sync(0xffffffffu, sum1, 1);
            sum1 += __shfl_xor_sync(0xffffffffu, sum1, 2);
            l0 = l0 * corr0 + sum0;
            l1 = l1 * corr1 + sum1;

            #pragma unroll
            for (int nf = 0; nf < 8; nf++) {
                o[nf][0] *= corr0; o[nf][1] *= corr0;
                o[nf][2] *= corr1; o[nf][3] *= corr1;
            }

            #pragma unroll
            for (int ks = 0; ks < 4; ks++) {
                unsigned vb[8][2];
                #pragma unroll
                for (int j = 0; j < 4; j++) {
                    const __half* p = &Vs[st][8 * (2 * ks + (g & 1)) + r]
                                         [8 * (2 * j + (g >> 1))];
                    ldsm4t(vb[2 * j][0], vb[2 * j][1],
                           vb[2 * j + 1][0], vb[2 * j + 1][1], p);
                }
                unsigned pa[4] = { ph[2 * ks][0], ph[2 * ks][1],
                                   ph[2 * ks + 1][0], ph[2 * ks + 1][1] };
                #pragma unroll
                for (int nf = 0; nf < 8; nf++) mma_f16(o[nf], pa, vb[nf]);
            }
        }
        __syncthreads();
    }
    #undef APREFETCH

    const float inv0 = 1.0f / l0;
    const float inv1 = 1.0f / l1;
    __half* yb = y + ((size_t)(b * T_) + rbase) * E_ + h * HD_;
    #pragma unroll
    for (int nf = 0; nf < 8; nf++) {
        const int d = nf * 8 + 2 * tig;
        *reinterpret_cast<__half2*>(yb + (size_t)gid * E_ + d)
            = __floats2half2_rn(o[nf][0] * inv0, o[nf][1] * inv0);
        *reinterpret_cast<__half2*>(yb + (size_t)(gid + 8) * E_ + d)
            = __floats2half2_rn(o[nf][2] * inv1, o[nf][3] * inv1);
    }
}

// ---------------------------------------------------------------------------
// kernel_launch
// ---------------------------------------------------------------------------
extern "C" void kernel_launch(void* const* d_in, const int* in_sizes, int n_in,
                              void* d_out, int out_size)
{
    (void)in_sizes; (void)n_in; (void)out_size;
    const float* x      = (const float*)d_in[0];
    const float* ln1_g  = (const float*)d_in[1];
    const float* ln1_b  = (const float*)d_in[2];
    const float* w_attn = (const float*)d_in[3];
    const float* b_attn = (const float*)d_in[4];
    const float* w_proj = (const float*)d_in[5];
    const float* b_proj = (const float*)d_in[6];
    const float* ln2_g  = (const float*)d_in[7];
    const float* ln2_b  = (const float*)d_in[8];
    const float* w_fc   = (const float*)d_in[9];
    const float* b_fc   = (const float*)d_in[10];
    const float* w_fc2  = (const float*)d_in[11];
    const float* b_fc2  = (const float*)d_in[12];
    float* out = (float*)d_out;

    __half *h, *qkvh, *y, *fc, *wh;
    float *x1;
    cudaGetSymbolAddress((void**)&h,    g_h);
    cudaGetSymbolAddress((void**)&qkvh, g_qkvh);
    cudaGetSymbolAddress((void**)&y,    g_y);
    cudaGetSymbolAddress((void**)&x1,   g_x1);
    cudaGetSymbolAddress((void**)&fc,   g_fc);
    cudaGetSymbolAddress((void**)&wh,   g_wh);

    __half* wh_attn = wh;
    __half* wh_proj = wh + 3 * E_ * E_;
    __half* wh_fc   = wh + 4 * E_ * E_;
    __half* wh_fc2  = wh + 8 * E_ * E_;

    // 0. convert weights to fp16
    f2h_kernel<<<(3 * E_ * E_ / 4 + 255) / 256, 256>>>(w_attn, wh_attn, 3 * E_ * E_ / 4);
    f2h_kernel<<<(E_ * E_ / 4 + 255) / 256, 256>>>(w_proj, wh_proj, E_ * E_ / 4);
    f2h_kernel<<<(4 * E_ * E_ / 4 + 255) / 256, 256>>>(w_fc,  wh_fc,  4 * E_ * E_ / 4);
    f2h_kernel<<<(4 * E_ * E_ / 4 + 255) / 256, 256>>>(w_fc2, wh_fc2, 4 * E_ * E_ / 4);

    // 1. ln1 (fp16 out)
    ln_kernel<<<BT_, 256>>>(x, ln1_g, ln1_b, h);
    // 2. qkv = h @ w_attn + b_attn (fp16 out)
    hgemm_kernel<false, false, true><<<dim3(3 * E_ / 128, BT_ / 128), 256>>>(
        BT_, 3 * E_, E_, h, wh_attn, b_attn, nullptr, nullptr, qkvh);
    // 3. causal MHA (fp16 out)
    attn_kernel<<<dim3(T_ / 128, H_, B_), 256>>>(qkvh, y);
    // 4. x1 = x + y @ w_proj + b_proj (fp32 out)
    hgemm_kernel<false, true, false><<<dim3(E_ / 128, BT_ / 128), 256>>>(
        BT_, E_, E_, y, wh_proj, b_proj, x, x1, nullptr);
    // 5. ln2 (fp16 out)
    ln_kernel<<<BT_, 256>>>(x1, ln2_g, ln2_b, h);
    // 6. fc = gelu(h @ w_fc + b_fc) (fp16 out)
    hgemm_kernel<true, false, true><<<dim3(4 * E_ / 128, BT_ / 128), 256>>>(
        BT_, 4 * E_, E_, h, wh_fc, b_fc, nullptr, nullptr, fc);
    // 7. out = x1 + fc @ w_fc2 + b_fc2 (fp32 out)
    hgemm_kernel<false, true, false><<<dim3(E_ / 128, BT_ / 128), 256>>>(
        BT_, E_, 4 * E_, fc, wh_fc2, b_fc2, x1, out, nullptr);
}